// round 14
// baseline (speedup 1.0000x reference)
#include <cuda_runtime.h>
#include <cuda_bf16.h>
#include <math.h>
#include <stdint.h>

#define BATCH 2
#define SEQ   2048
#define NHEAD 16
#define DK    64
#define DM    1024
#define MTOT  (BATCH*SEQ)   // 4096
#define NKS   32            // 1024 / 32 k-steps

// ---------------------------------------------------------------------------
// Scratch (allocation-free)
// ---------------------------------------------------------------------------
__device__ float g_q [BATCH*NHEAD*SEQ*DK];   // [B,H,S,DK]
__device__ float g_ao[MTOT*DM];              // A-frag-major [mblk][kt][4096]
__device__ float g_xp[MTOT*DM];              // x, A-frag-major, tf32-rounded
__device__ float g_wp[4*DM*DM];              // W, B-frag-major, tf32-rounded
// frag-major packed bf16 K and V: [bh][tile][frag=ks*8+nf][lane] x uint4
__device__ uint32_t g_kp[32*32*32*32*4];     // 16 MB
__device__ uint32_t g_vp[32*32*32*32*4];     // 16 MB

// ---------------------------------------------------------------------------
// Helpers
// ---------------------------------------------------------------------------
__device__ __forceinline__ uint32_t smem_u32(const void* p) {
    uint32_t a;
    asm("{ .reg .u64 t; cvta.to.shared.u64 t, %1; cvt.u32.u64 %0, t; }"
        : "=r"(a) : "l"(p));
    return a;
}
__device__ __forceinline__ float rna_tf32(float x) {
    float y; asm("cvt.rna.tf32.f32 %0, %1;" : "=f"(y) : "f"(x)); return y;
}

#define CP_ASYNC16(sm, gp) \
    asm volatile("cp.async.cg.shared.global [%0], [%1], 16;" :: "r"(sm), "l"(gp) : "memory")
#define CP_COMMIT() asm volatile("cp.async.commit_group;" ::: "memory")
#define CP_WAIT0()  asm volatile("cp.async.wait_group 0;" ::: "memory")

__device__ __forceinline__ void mma_tf32(float c[4], const uint32_t a[4],
                                         const uint32_t b[2]) {
    asm volatile(
        "mma.sync.aligned.m16n8k8.row.col.f32.tf32.tf32.f32 "
        "{%0,%1,%2,%3}, {%4,%5,%6,%7}, {%8,%9}, {%0,%1,%2,%3};"
        : "+f"(c[0]), "+f"(c[1]), "+f"(c[2]), "+f"(c[3])
        : "r"(a[0]), "r"(a[1]), "r"(a[2]), "r"(a[3]), "r"(b[0]), "r"(b[1]));
}

__device__ __forceinline__ void mma_bf16(float c[4], const uint32_t a[4],
                                         uint32_t b0, uint32_t b1) {
    asm volatile(
        "mma.sync.aligned.m16n8k16.row.col.f32.bf16.bf16.f32 "
        "{%0,%1,%2,%3}, {%4,%5,%6,%7}, {%8,%9}, {%0,%1,%2,%3};"
        : "+f"(c[0]), "+f"(c[1]), "+f"(c[2]), "+f"(c[3])
        : "r"(a[0]), "r"(a[1]), "r"(a[2]), "r"(a[3]), "r"(b0), "r"(b1));
}

__device__ __forceinline__ uint32_t packbf(float lo, float hi) {
    __nv_bfloat162 t = __floats2bfloat162_rn(lo, hi);
    return *(uint32_t*)&t;
}
__device__ __forceinline__ float bflo(uint32_t r) { return __uint_as_float(r << 16); }
__device__ __forceinline__ float bfhi(uint32_t r) { return __uint_as_float(r & 0xFFFF0000u); }
__device__ __forceinline__ uint32_t packpair(float x0, float x1, uint32_t& lo) {
    uint32_t hi = packbf(x0, x1);
    lo = packbf(x0 - bflo(hi), x1 - bfhi(hi));
    return hi;
}

// 2^(z-16) on fixed-lat pipes
__device__ __forceinline__ float fexp2m(float z) {
    float zz = z - 16.f;
    float t = zz + 12582912.f;
    int   e = __float_as_int(t) << 23;
    float f = zz - (t - 12582912.f);
    float w = f * 0.69314718056f;
    float p = 1.f + w * (1.f + w * (0.5f + w * (0.166666667f + w * 0.0416666667f)));
    return __int_as_float(__float_as_int(p) + e);
}

// ---------------------------------------------------------------------------
// perm_all (unchanged)
// ---------------------------------------------------------------------------
__global__ void __launch_bounds__(256)
perm_all(const float* __restrict__ x,
         const float* __restrict__ wq, const float* __restrict__ wk,
         const float* __restrict__ wv, const float* __restrict__ wo)
{
    __shared__ float vs[128][33];
    const int bid = blockIdx.x;
    const int tid = threadIdx.x;
    const bool isx = (bid < 1024);
    const float* src;
    int kt, mblk = 0, w = 0, nblk = 0;
    if (isx) {
        mblk = bid >> 5; kt = bid & 31;
        src = x + (size_t)(mblk * 128) * DM + kt * 32;
    } else {
        int t = bid - 1024;
        w = t >> 8; nblk = (t >> 5) & 7; kt = t & 31;
        const float* W = (w == 0) ? wq : (w == 1) ? wk : (w == 2) ? wv : wo;
        src = W + (size_t)(nblk * 128) * DM + kt * 32;
    }

    #pragma unroll
    for (int t = 0; t < 4; ++t) {
        int i4 = tid + t * 256;
        int r = i4 >> 3, c4 = (i4 & 7) * 4;
        float4 v = *(const float4*)&src[(size_t)r * DM + c4];
        vs[r][c4]     = rna_tf32(v.x);
        vs[r][c4 + 1] = rna_tf32(v.y);
        vs[r][c4 + 2] = rna_tf32(v.z);
        vs[r][c4 + 3] = rna_tf32(v.w);
    }
    __syncthreads();

    if (isx) {
        float4* dst = (float4*)g_xp + ((size_t)mblk * 32 + kt) * 1024;
        #pragma unroll
        for (int t = 0; t < 4; ++t) {
            int f = tid + t * 256;
            int frag = f >> 5, lane = f & 31;
            int g = lane >> 2, tg = lane & 3;
            int mfa = frag >> 2, ks = frag & 3;
            int r0 = mfa * 16 + g, c0 = ks * 8 + tg;
            dst[f] = make_float4(vs[r0][c0], vs[r0 + 8][c0],
                                 vs[r0][c0 + 4], vs[r0 + 8][c0 + 4]);
        }
    } else {
        float2* dst = (float2*)g_wp + (((size_t)w * 8 + nblk) * 32 + kt) * 2048;
        #pragma unroll
        for (int t = 0; t < 8; ++t) {
            int f = tid + t * 256;
            int frag = f >> 5, lane = f & 31;
            int g = lane >> 2, tg = lane & 3;
            int nf = frag >> 2, ks = frag & 3;
            int nl = nf * 8 + g, c0 = ks * 8 + tg;
            dst[f] = make_float2(vs[nl][c0], vs[nl][c0 + 4]);
        }
    }
}

// ---------------------------------------------------------------------------
// GEMM core (tf32 mma.sync, frag-major operands) — now 3 CTAs/SM
// ---------------------------------------------------------------------------
#define GEMM_SMEM 65536

__device__ __forceinline__ void gload(uint32_t sbase,
                                      const float* __restrict__ A,
                                      const float* __restrict__ B,
                                      int m0, int n0, int kt, int tid, int buf) {
    const float* As = A + ((size_t)(m0 >> 7) * 32 + kt) * 4096;
    const float* Bs = B + ((size_t)(n0 >> 7) * 32 + kt) * 4096;
    const uint32_t abuf = sbase + buf * 32768;
    const uint32_t bbuf = abuf + 16384;
    #pragma unroll
    for (int i = 0; i < 4; ++i) {
        int o = tid + i * 256;
        CP_ASYNC16(abuf + o * 16, As + o * 4);
        CP_ASYNC16(bbuf + o * 16, Bs + o * 4);
    }
    CP_COMMIT();
}

struct GemmCtx {
    int tid, lane, warp, gid, tig, warpM, warpN, m0, n0;
};

__device__ __forceinline__ void gctx_init(GemmCtx& g) {
    g.tid   = threadIdx.x;
    g.lane  = g.tid & 31;
    g.warp  = g.tid >> 5;
    g.gid   = g.lane >> 2;
    g.tig   = g.lane & 3;
    g.warpM = g.warp & 1;
    g.warpN = g.warp >> 1;
    g.m0 = blockIdx.y * 128;
    g.n0 = blockIdx.x * 128;
}

__device__ __forceinline__ void gemm_main(const float* __restrict__ A,
                                          const float* __restrict__ B,
                                          float* sh, uint32_t sbase,
                                          const GemmCtx& g, float c[4][4][4]) {
    #pragma unroll
    for (int i = 0; i < 4; ++i)
        #pragma unroll
        for (int j = 0; j < 4; ++j)
            #pragma unroll
            for (int k = 0; k < 4; ++k) c[i][j][k] = 0.f;

    gload(sbase, A, B, g.m0, g.n0, 0, g.tid, 0);

    for (int kt = 0; kt < NKS; ++kt) {
        const int buf = kt & 1;
        CP_WAIT0();
        __syncthreads();
        if (kt + 1 < NKS)
            gload(sbase, A, B, g.m0, g.n0, kt + 1, g.tid, buf ^ 1);

        const float* Ab = sh + buf * 8192;
        const float* Bb = Ab + 4096;

        #pragma unroll
        for (int ks = 0; ks < 4; ++ks) {
            uint32_t a[4][4], b[4][2];
            #pragma unroll
            for (int mf = 0; mf < 4; ++mf) {
                float4 av = *(const float4*)
                    &Ab[((((g.warpM * 4 + mf) * 4 + ks) * 32) + g.lane) * 4];
                a[mf][0] = __float_as_uint(av.x);
                a[mf][1] = __float_as_uint(av.y);
                a[mf][2] = __float_as_uint(av.z);
                a[mf][3] = __float_as_uint(av.w);
            }
            #pragma unroll
            for (int nf = 0; nf < 4; ++nf) {
                float2 bv = *(const float2*)
                    &Bb[((((g.warpN * 4 + nf) * 4 + ks) * 32) + g.lane) * 2];
                b[nf][0] = __float_as_uint(bv.x);
                b[nf][1] = __float_as_uint(bv.y);
            }
            #pragma unroll
            for (int mf = 0; mf < 4; ++mf)
                #pragma unroll
                for (int nf = 0; nf < 4; ++nf)
                    mma_tf32(c[mf][nf], a[mf], b[nf]);
        }
    }
}

// ---------------------------------------------------------------------------
// Fused QKV GEMM (epilogues unchanged)
// ---------------------------------------------------------------------------
__global__ void __launch_bounds__(256, 3)
gemm_qkv_fused(const float* __restrict__ cosT, const float* __restrict__ sinT,
               const int* __restrict__ pos)
{
    extern __shared__ float sh[];
    const uint32_t sbase = smem_u32(sh);
    const int z = blockIdx.z;
    GemmCtx g; gctx_init(g);

    float c[4][4][4];
    gemm_main(g_xp, g_wp + (size_t)z * DM * DM, sh, sbase, g, c);

    const unsigned FULL = 0xffffffffu;

    #pragma unroll
    for (int mf = 0; mf < 4; ++mf) {
        #pragma unroll
        for (int half = 0; half < 2; ++half) {
            int m = g.m0 + g.warpM * 64 + mf * 16 + half * 8 + g.gid;
            int b_ = m >> 11;
            int s  = m & (SEQ - 1);
            int p  = (z != 2) ? pos[s] : 0;
            #pragma unroll
            for (int nf = 0; nf < 4; ++nf) {
                int n = g.n0 + g.warpN * 32 + nf * 8 + 2 * g.tig;   // even
                float e = c[mf][nf][half * 2 + 0];
                float o = c[mf][nf][half * 2 + 1];
                int h = n >> 6;
                int d = n & 63;
                if (z != 2) {
                    float cs = cosT[p * DK + d];
                    float sn = sinT[p * DK + d];
                    float oe = e * cs - o * sn;
                    float oo = o * cs + e * sn;
                    e = oe; o = oo;
                }
                int bh = b_ * NHEAD + h;
                if (z == 0) {
                    *(float2*)&g_q[(((size_t)bh * SEQ + s) << 6) + d] =
                        make_float2(e, o);
                } else if (z == 1) {
                    int kt  = s >> 6, st = s & 63;
                    int nfk = st >> 3, gidk = st & 7;
                    int pp  = d >> 1;
                    int ks  = pp >> 3, rem = pp & 7;
                    int wsel = rem >> 2, tigk = rem & 3;
                    uint32_t lo, hi = packpair(e, o, lo);
                    size_t u = ((((size_t)bh * 32 + kt) * 32 + ks * 8 + nfk) * 32
                                + gidk * 4 + tigk) * 4;
                    g_kp[u + wsel]     = hi;
                    g_kp[u + 2 + wsel] = lo;
                } else {
                    float pe = __shfl_xor_sync(FULL, e, 4);
                    float po = __shfl_xor_sync(FULL, o, 4);
                    if ((g.gid & 1) == 0) {
                        int kt = s >> 6;
                        int pl = (s & 63) >> 1;
                        int ks = pl >> 3, rem = pl & 7;
                        int wsel = rem >> 2, tigk = rem & 3;
                        {
                            int df = d >> 3, gidk = d & 7;
                            uint32_t lo, hi = packpair(e, pe, lo);
                            size_t u = ((((size_t)bh * 32 + kt) * 32 + ks * 8 + df) * 32
                                        + gidk * 4 + tigk) * 4;
                            g_vp[u + wsel]     = hi;
                            g_vp[u + 2 + wsel] = lo;
                        }
                        {
                            int d1 = d + 1;
                            int df = d1 >> 3, gidk = d1 & 7;
                            uint32_t lo, hi = packpair(o, po, lo);
                            size_t u = ((((size_t)bh * 32 + kt) * 32 + ks * 8 + df) * 32
                                        + gidk * 4 + tigk) * 4;
                            g_vp[u + wsel]     = hi;
                            g_vp[u + 2 + wsel] = lo;
                        }
                    }
                }
            }
        }
    }
}

// ---------------------------------------------------------------------------
// Output GEMM (unchanged epilogue)
// ---------------------------------------------------------------------------
__global__ void __launch_bounds__(256, 3)
gemm_out(float* __restrict__ out)
{
    extern __shared__ float sh[];
    const uint32_t sbase = smem_u32(sh);
    GemmCtx g; gctx_init(g);

    float c[4][4][4];
    gemm_main(g_ao, g_wp + (size_t)3 * DM * DM, sh, sbase, g, c);

    #pragma unroll
    for (int mf = 0; mf < 4; ++mf) {
        #pragma unroll
        for (int half = 0; half < 2; ++half) {
            int m = g.m0 + g.warpM * 64 + mf * 16 + half * 8 + g.gid;
            #pragma unroll
            for (int nf = 0; nf < 4; ++nf) {
                int n = g.n0 + g.warpN * 32 + nf * 8 + 2 * g.tig;
                *(float2*)&out[(size_t)m * DM + n] =
                    make_float2(c[mf][nf][half * 2], c[mf][nf][half * 2 + 1]);
            }
        }
    }
}

// ---------------------------------------------------------------------------
// Tensor-core causal flash attention — Q-tile 128 (8 warps), K-tile 64.
// Halves barrier/fload/L2 cost per unit compute. smem 64 KB -> 3 CTAs/SM.
// ---------------------------------------------------------------------------
#define FBUF 8192                      // u32 per buffer
#define FTC_SMEM (2 * FBUF * 4)        // 65536 B

__device__ __forceinline__ void fload(uint32_t sbase, int bh, int kt,
                                      int buf, int tid)
{
    const uint32_t* ksrc = g_kp + (((size_t)bh * 32 + kt) * 1024) * 4;
    const uint32_t* vsrc = g_vp + (((size_t)bh * 32 + kt) * 1024) * 4;
    #pragma unroll
    for (int t = 0; t < 8; ++t) {
        int id = tid + t * 256;          // uint4 index 0..2047
        const uint32_t* src = (id < 1024) ? (ksrc + id * 4)
                                          : (vsrc + (id - 1024) * 4);
        CP_ASYNC16(sbase + buf * (FBUF * 4) + id * 16, src);
    }
    CP_COMMIT();
}

__global__ void __launch_bounds__(256, 3) flash_tc()
{
    extern __shared__ uint32_t smu[];
    const uint32_t sbase = smem_u32(smu);
    const int tid  = threadIdx.x;
    const int lane = tid & 31;
    const int warp = tid >> 5;           // 0..7
    const int gid  = lane >> 2;
    const int tig  = lane & 3;
    const int qi   = 15 - blockIdx.x;    // heavy q-tiles first
    const int bh   = blockIdx.y;
    const int q0   = qi * 128;
    const int rmin = q0 + warp * 16;     // warp's lowest q row
    const int ktmax = 2 * qi + 1;        // inclusive

    const float* qg = g_q + (size_t)bh * SEQ * DK;

    const float QSCALE = 0.125f * 1.44269504f;
    uint32_t qh[4][4], ql[4][4];
    #pragma unroll
    for (int ks = 0; ks < 4; ++ks) {
        #pragma unroll
        for (int j = 0; j < 4; ++j) {
            int row = rmin + gid + (j & 1) * 8;
            int col = ks * 16 + 2 * tig + (j >> 1) * 8;
            float2 v = *(const float2*)&qg[(size_t)row * DK + col];
            v.x *= QSCALE; v.y *= QSCALE;
            qh[ks][j] = packpair(v.x, v.y, ql[ks][j]);
        }
    }

    float O[8][4];
    #pragma unroll
    for (int i = 0; i < 8; ++i)
        #pragma unroll
        for (int j = 0; j < 4; ++j) O[i][j] = 0.f;
    float lrow[2] = {0.f, 0.f};

    fload(sbase, bh, 0, 0, tid);

    for (int kt = 0; kt <= ktmax; ++kt) {
        const int buf = kt & 1;
        CP_WAIT0();
        __syncthreads();
        if (kt < ktmax)
            fload(sbase, bh, kt + 1, buf ^ 1, tid);

        const int k0 = kt * 64;
        if (k0 > rmin + 15) continue;    // fully masked for this warp

        const uint4* Kb = (const uint4*)(smu + buf * FBUF);
        const uint4* Vb = Kb + 1024;

        float S[8][4];
        #pragma unroll
        for (int i = 0; i < 8; ++i)
            #pragma unroll
            for (int j = 0; j < 4; ++j) S[i][j] = 0.f;

        #pragma unroll
        for (int ks = 0; ks < 4; ++ks) {
            #pragma unroll
            for (int nf = 0; nf < 8; ++nf) {
                uint4 kw = Kb[(ks * 8 + nf) * 32 + lane];
                mma_bf16(S[nf], qh[ks], kw.x, kw.y);
                mma_bf16(S[nf], qh[ks], kw.z, kw.w);
                mma_bf16(S[nf], ql[ks], kw.x, kw.y);
            }
        }

        const bool needmask = (k0 + 63 > rmin);
        #pragma unroll
        for (int nf = 0; nf < 8; ++nf)
            #pragma unroll
            for (int j = 0; j < 4; ++j) {
                float e = fexp2m(S[nf][j]);
                if (needmask) {
                    int col = k0 + nf * 8 + 2 * tig + (j & 1);
                    int row = rmin + gid + (j >> 1) * 8;
                    if (col > row) e = 0.f;
                }
                S[nf][j] = e;
                lrow[j >> 1] += e;
            }

        #pragma unroll
        for (int ks = 0; ks < 4; ++ks) {
            uint32_t aH[4], aL[4];
            #pragma unroll
            for (int h = 0; h < 2; ++h) {
                aH[2*h]   = packpair(S[2*ks+h][0], S[2*ks+h][1], aL[2*h]);
                aH[2*h+1] = packpair(S[2*ks+h][2], S[2*ks+h][3], aL[2*h+1]);
            }
            #pragma unroll
            for (int df = 0; df < 8; ++df) {
                uint4 vw = Vb[(ks * 8 + df) * 32 + lane];
                mma_bf16(O[df], aH, vw.x, vw.y);
                mma_bf16(O[df], aH, vw.z, vw.w);
                mma_bf16(O[df], aL, vw.x, vw.y);
            }
        }
    }

    const unsigned FULL = 0xffffffffu;
    #pragma unroll
    for (int r = 0; r < 2; ++r) {
        lrow[r] += __shfl_xor_sync(FULL, lrow[r], 1);
        lrow[r] += __shfl_xor_sync(FULL, lrow[r], 2);
    }
    const int b = bh >> 4;
    const int h = bh & 15;
    #pragma unroll
    for (int r = 0; r < 2; ++r) {
        float inv = 1.f / lrow[r];
        int s = rmin + gid + r * 8;
        int m = b * SEQ + s;
        int mblk = m >> 7;
        int rr   = m & 127;
        int mfa  = rr >> 4;
        int gg   = rr & 7;
        int hlf  = (rr >> 3) & 1;
        int ch   = tig >> 1;
        int t    = 2 * (tig & 1);
        #pragma unroll
        for (int df = 0; df < 8; ++df) {
            int col = h * 64 + df * 8 + 2 * tig;
            int kt  = col >> 5;
            int ks  = df & 3;
            size_t base = ((size_t)mblk * 32 + kt) * 4096 +
                          (((mfa * 4 + ks) * 32 + gg * 4 + t) * 4 + 2 * ch + hlf);
            g_ao[base]     = rna_tf32(O[df][2 * r]     * inv);
            g_ao[base + 4] = rna_tf32(O[df][2 * r + 1] * inv);
        }
    }
}

// ---------------------------------------------------------------------------
// Launcher
// ---------------------------------------------------------------------------
extern "C" void kernel_launch(void* const* d_in, const int* in_sizes, int n_in,
                              void* d_out, int out_size)
{
    const float* x    = (const float*)d_in[0];
    const float* Wq   = (const float*)d_in[1];
    const float* Wk   = (const float*)d_in[2];
    const float* Wv   = (const float*)d_in[3];
    const float* Wo   = (const float*)d_in[4];
    const float* cosT = (const float*)d_in[5];
    const float* sinT = (const float*)d_in[6];
    const int*   pos  = (const int*)  d_in[7];
    float*       out  = (float*)d_out;

    cudaFuncSetAttribute(flash_tc,
                         cudaFuncAttributeMaxDynamicSharedMemorySize, FTC_SMEM);
    cudaFuncSetAttribute(gemm_qkv_fused,
                         cudaFuncAttributeMaxDynamicSharedMemorySize, GEMM_SMEM);
    cudaFuncSetAttribute(gemm_out,
                         cudaFuncAttributeMaxDynamicSharedMemorySize, GEMM_SMEM);

    perm_all<<<2048, 256>>>(x, Wq, Wk, Wv, Wo);

    dim3 qgrid(DM / 128, MTOT / 128, 3);   // (8, 32, 3)
    gemm_qkv_fused<<<qgrid, 256, GEMM_SMEM>>>(cosT, sinT, pos);

    dim3 fgrid(SEQ / 128, BATCH * NHEAD);  // (16, 32)
    flash_tc<<<fgrid, 256, FTC_SMEM>>>();

    dim3 ogrid(DM / 128, MTOT / 128);      // (8, 32)
    gemm_out<<<ogrid, 256, GEMM_SMEM>>>(out);
}

// round 15
// speedup vs baseline: 1.6080x; 1.6080x over previous
#include <cuda_runtime.h>
#include <cuda_bf16.h>
#include <math.h>
#include <stdint.h>

#define BATCH 2
#define SEQ   2048
#define NHEAD 16
#define DK    64
#define DM    1024
#define MTOT  (BATCH*SEQ)   // 4096
#define NKS   32            // 1024 / 32 k-steps

// ---------------------------------------------------------------------------
// Scratch (allocation-free)
// ---------------------------------------------------------------------------
__device__ float g_q [BATCH*NHEAD*SEQ*DK];   // [B,H,S,DK]
__device__ float g_ao[MTOT*DM];              // A-frag-major [mblk][kt][4096]
__device__ float g_xp[MTOT*DM];              // x, A-frag-major, tf32-rounded
__device__ float g_wp[4*DM*DM];              // W, B-frag-major, tf32-rounded
// frag-major packed bf16 K and V: [bh][tile][frag=ks*8+nf][lane] x uint4
__device__ uint32_t g_kp[32*32*32*32*4];     // 16 MB
__device__ uint32_t g_vp[32*32*32*32*4];     // 16 MB

// ---------------------------------------------------------------------------
// Helpers
// ---------------------------------------------------------------------------
__device__ __forceinline__ uint32_t smem_u32(const void* p) {
    uint32_t a;
    asm("{ .reg .u64 t; cvta.to.shared.u64 t, %1; cvt.u32.u64 %0, t; }"
        : "=r"(a) : "l"(p));
    return a;
}
__device__ __forceinline__ float rna_tf32(float x) {
    float y; asm("cvt.rna.tf32.f32 %0, %1;" : "=f"(y) : "f"(x)); return y;
}

#define CP_ASYNC16(sm, gp) \
    asm volatile("cp.async.cg.shared.global [%0], [%1], 16;" :: "r"(sm), "l"(gp) : "memory")
#define CP_COMMIT() asm volatile("cp.async.commit_group;" ::: "memory")
#define CP_WAIT0()  asm volatile("cp.async.wait_group 0;" ::: "memory")

__device__ __forceinline__ void mma_tf32(float c[4], const uint32_t a[4],
                                         const uint32_t b[2]) {
    asm volatile(
        "mma.sync.aligned.m16n8k8.row.col.f32.tf32.tf32.f32 "
        "{%0,%1,%2,%3}, {%4,%5,%6,%7}, {%8,%9}, {%0,%1,%2,%3};"
        : "+f"(c[0]), "+f"(c[1]), "+f"(c[2]), "+f"(c[3])
        : "r"(a[0]), "r"(a[1]), "r"(a[2]), "r"(a[3]), "r"(b[0]), "r"(b[1]));
}

__device__ __forceinline__ void mma_bf16(float c[4], const uint32_t a[4],
                                         uint32_t b0, uint32_t b1) {
    asm volatile(
        "mma.sync.aligned.m16n8k16.row.col.f32.bf16.bf16.f32 "
        "{%0,%1,%2,%3}, {%4,%5,%6,%7}, {%8,%9}, {%0,%1,%2,%3};"
        : "+f"(c[0]), "+f"(c[1]), "+f"(c[2]), "+f"(c[3])
        : "r"(a[0]), "r"(a[1]), "r"(a[2]), "r"(a[3]), "r"(b0), "r"(b1));
}

__device__ __forceinline__ uint32_t packbf(float lo, float hi) {
    __nv_bfloat162 t = __floats2bfloat162_rn(lo, hi);
    return *(uint32_t*)&t;
}
__device__ __forceinline__ float bflo(uint32_t r) { return __uint_as_float(r << 16); }
__device__ __forceinline__ float bfhi(uint32_t r) { return __uint_as_float(r & 0xFFFF0000u); }
__device__ __forceinline__ uint32_t packpair(float x0, float x1, uint32_t& lo) {
    uint32_t hi = packbf(x0, x1);
    lo = packbf(x0 - bflo(hi), x1 - bfhi(hi));
    return hi;
}

// 2^(z-16) on fixed-lat pipes
__device__ __forceinline__ float fexp2m(float z) {
    float zz = z - 16.f;
    float t = zz + 12582912.f;
    int   e = __float_as_int(t) << 23;
    float f = zz - (t - 12582912.f);
    float w = f * 0.69314718056f;
    float p = 1.f + w * (1.f + w * (0.5f + w * (0.166666667f + w * 0.0416666667f)));
    return __int_as_float(__float_as_int(p) + e);
}

// ---------------------------------------------------------------------------
// perm_all
// ---------------------------------------------------------------------------
__global__ void __launch_bounds__(256)
perm_all(const float* __restrict__ x,
         const float* __restrict__ wq, const float* __restrict__ wk,
         const float* __restrict__ wv, const float* __restrict__ wo)
{
    __shared__ float vs[128][33];
    const int bid = blockIdx.x;
    const int tid = threadIdx.x;
    const bool isx = (bid < 1024);
    const float* src;
    int kt, mblk = 0, w = 0, nblk = 0;
    if (isx) {
        mblk = bid >> 5; kt = bid & 31;
        src = x + (size_t)(mblk * 128) * DM + kt * 32;
    } else {
        int t = bid - 1024;
        w = t >> 8; nblk = (t >> 5) & 7; kt = t & 31;
        const float* W = (w == 0) ? wq : (w == 1) ? wk : (w == 2) ? wv : wo;
        src = W + (size_t)(nblk * 128) * DM + kt * 32;
    }

    #pragma unroll
    for (int t = 0; t < 4; ++t) {
        int i4 = tid + t * 256;
        int r = i4 >> 3, c4 = (i4 & 7) * 4;
        float4 v = *(const float4*)&src[(size_t)r * DM + c4];
        vs[r][c4]     = rna_tf32(v.x);
        vs[r][c4 + 1] = rna_tf32(v.y);
        vs[r][c4 + 2] = rna_tf32(v.z);
        vs[r][c4 + 3] = rna_tf32(v.w);
    }
    __syncthreads();

    if (isx) {
        float4* dst = (float4*)g_xp + ((size_t)mblk * 32 + kt) * 1024;
        #pragma unroll
        for (int t = 0; t < 4; ++t) {
            int f = tid + t * 256;
            int frag = f >> 5, lane = f & 31;
            int g = lane >> 2, tg = lane & 3;
            int mfa = frag >> 2, ks = frag & 3;
            int r0 = mfa * 16 + g, c0 = ks * 8 + tg;
            dst[f] = make_float4(vs[r0][c0], vs[r0 + 8][c0],
                                 vs[r0][c0 + 4], vs[r0 + 8][c0 + 4]);
        }
    } else {
        float2* dst = (float2*)g_wp + (((size_t)w * 8 + nblk) * 32 + kt) * 2048;
        #pragma unroll
        for (int t = 0; t < 8; ++t) {
            int f = tid + t * 256;
            int frag = f >> 5, lane = f & 31;
            int g = lane >> 2, tg = lane & 3;
            int nf = frag >> 2, ks = frag & 3;
            int nl = nf * 8 + g, c0 = ks * 8 + tg;
            dst[f] = make_float2(vs[nl][c0], vs[nl][c0 + 4]);
        }
    }
}

// ---------------------------------------------------------------------------
// GEMM core (tf32 mma.sync, frag-major operands) — single-sync, 2 CTAs/SM
// (2 CTAs is the register-file limit: 256 thr x 124 regs x 2 = 63.5K)
// ---------------------------------------------------------------------------
#define GEMM_SMEM 65536

__device__ __forceinline__ void gload(uint32_t sbase,
                                      const float* __restrict__ A,
                                      const float* __restrict__ B,
                                      int m0, int n0, int kt, int tid, int buf) {
    const float* As = A + ((size_t)(m0 >> 7) * 32 + kt) * 4096;
    const float* Bs = B + ((size_t)(n0 >> 7) * 32 + kt) * 4096;
    const uint32_t abuf = sbase + buf * 32768;
    const uint32_t bbuf = abuf + 16384;
    #pragma unroll
    for (int i = 0; i < 4; ++i) {
        int o = tid + i * 256;
        CP_ASYNC16(abuf + o * 16, As + o * 4);
        CP_ASYNC16(bbuf + o * 16, Bs + o * 4);
    }
    CP_COMMIT();
}

struct GemmCtx {
    int tid, lane, warp, gid, tig, warpM, warpN, m0, n0;
};

__device__ __forceinline__ void gctx_init(GemmCtx& g) {
    g.tid   = threadIdx.x;
    g.lane  = g.tid & 31;
    g.warp  = g.tid >> 5;
    g.gid   = g.lane >> 2;
    g.tig   = g.lane & 3;
    g.warpM = g.warp & 1;
    g.warpN = g.warp >> 1;
    g.m0 = blockIdx.y * 128;
    g.n0 = blockIdx.x * 128;
}

__device__ __forceinline__ void gemm_main(const float* __restrict__ A,
                                          const float* __restrict__ B,
                                          float* sh, uint32_t sbase,
                                          const GemmCtx& g, float c[4][4][4]) {
    #pragma unroll
    for (int i = 0; i < 4; ++i)
        #pragma unroll
        for (int j = 0; j < 4; ++j)
            #pragma unroll
            for (int k = 0; k < 4; ++k) c[i][j][k] = 0.f;

    gload(sbase, A, B, g.m0, g.n0, 0, g.tid, 0);

    for (int kt = 0; kt < NKS; ++kt) {
        const int buf = kt & 1;
        CP_WAIT0();
        __syncthreads();
        if (kt + 1 < NKS)
            gload(sbase, A, B, g.m0, g.n0, kt + 1, g.tid, buf ^ 1);

        const float* Ab = sh + buf * 8192;
        const float* Bb = Ab + 4096;

        #pragma unroll
        for (int ks = 0; ks < 4; ++ks) {
            uint32_t a[4][4], b[4][2];
            #pragma unroll
            for (int mf = 0; mf < 4; ++mf) {
                float4 av = *(const float4*)
                    &Ab[((((g.warpM * 4 + mf) * 4 + ks) * 32) + g.lane) * 4];
                a[mf][0] = __float_as_uint(av.x);
                a[mf][1] = __float_as_uint(av.y);
                a[mf][2] = __float_as_uint(av.z);
                a[mf][3] = __float_as_uint(av.w);
            }
            #pragma unroll
            for (int nf = 0; nf < 4; ++nf) {
                float2 bv = *(const float2*)
                    &Bb[((((g.warpN * 4 + nf) * 4 + ks) * 32) + g.lane) * 2];
                b[nf][0] = __float_as_uint(bv.x);
                b[nf][1] = __float_as_uint(bv.y);
            }
            #pragma unroll
            for (int mf = 0; mf < 4; ++mf)
                #pragma unroll
                for (int nf = 0; nf < 4; ++nf)
                    mma_tf32(c[mf][nf], a[mf], b[nf]);
        }
    }
}

// ---------------------------------------------------------------------------
// Fused QKV GEMM
// ---------------------------------------------------------------------------
__global__ void __launch_bounds__(256, 2)
gemm_qkv_fused(const float* __restrict__ cosT, const float* __restrict__ sinT,
               const int* __restrict__ pos)
{
    extern __shared__ float sh[];
    const uint32_t sbase = smem_u32(sh);
    const int z = blockIdx.z;
    GemmCtx g; gctx_init(g);

    float c[4][4][4];
    gemm_main(g_xp, g_wp + (size_t)z * DM * DM, sh, sbase, g, c);

    const unsigned FULL = 0xffffffffu;

    #pragma unroll
    for (int mf = 0; mf < 4; ++mf) {
        #pragma unroll
        for (int half = 0; half < 2; ++half) {
            int m = g.m0 + g.warpM * 64 + mf * 16 + half * 8 + g.gid;
            int b_ = m >> 11;
            int s  = m & (SEQ - 1);
            int p  = (z != 2) ? pos[s] : 0;
            #pragma unroll
            for (int nf = 0; nf < 4; ++nf) {
                int n = g.n0 + g.warpN * 32 + nf * 8 + 2 * g.tig;   // even
                float e = c[mf][nf][half * 2 + 0];
                float o = c[mf][nf][half * 2 + 1];
                int h = n >> 6;
                int d = n & 63;
                if (z != 2) {
                    float cs = cosT[p * DK + d];
                    float sn = sinT[p * DK + d];
                    float oe = e * cs - o * sn;
                    float oo = o * cs + e * sn;
                    e = oe; o = oo;
                }
                int bh = b_ * NHEAD + h;
                if (z == 0) {
                    *(float2*)&g_q[(((size_t)bh * SEQ + s) << 6) + d] =
                        make_float2(e, o);
                } else if (z == 1) {
                    int kt  = s >> 6, st = s & 63;
                    int nfk = st >> 3, gidk = st & 7;
                    int pp  = d >> 1;
                    int ks  = pp >> 3, rem = pp & 7;
                    int wsel = rem >> 2, tigk = rem & 3;
                    uint32_t lo, hi = packpair(e, o, lo);
                    size_t u = ((((size_t)bh * 32 + kt) * 32 + ks * 8 + nfk) * 32
                                + gidk * 4 + tigk) * 4;
                    g_kp[u + wsel]     = hi;
                    g_kp[u + 2 + wsel] = lo;
                } else {
                    float pe = __shfl_xor_sync(FULL, e, 4);
                    float po = __shfl_xor_sync(FULL, o, 4);
                    if ((g.gid & 1) == 0) {
                        int kt = s >> 6;
                        int pl = (s & 63) >> 1;
                        int ks = pl >> 3, rem = pl & 7;
                        int wsel = rem >> 2, tigk = rem & 3;
                        {
                            int df = d >> 3, gidk = d & 7;
                            uint32_t lo, hi = packpair(e, pe, lo);
                            size_t u = ((((size_t)bh * 32 + kt) * 32 + ks * 8 + df) * 32
                                        + gidk * 4 + tigk) * 4;
                            g_vp[u + wsel]     = hi;
                            g_vp[u + 2 + wsel] = lo;
                        }
                        {
                            int d1 = d + 1;
                            int df = d1 >> 3, gidk = d1 & 7;
                            uint32_t lo, hi = packpair(o, po, lo);
                            size_t u = ((((size_t)bh * 32 + kt) * 32 + ks * 8 + df) * 32
                                        + gidk * 4 + tigk) * 4;
                            g_vp[u + wsel]     = hi;
                            g_vp[u + 2 + wsel] = lo;
                        }
                    }
                }
            }
        }
    }
}

// ---------------------------------------------------------------------------
// Output GEMM
// ---------------------------------------------------------------------------
__global__ void __launch_bounds__(256, 2)
gemm_out(float* __restrict__ out)
{
    extern __shared__ float sh[];
    const uint32_t sbase = smem_u32(sh);
    GemmCtx g; gctx_init(g);

    float c[4][4][4];
    gemm_main(g_ao, g_wp + (size_t)3 * DM * DM, sh, sbase, g, c);

    #pragma unroll
    for (int mf = 0; mf < 4; ++mf) {
        #pragma unroll
        for (int half = 0; half < 2; ++half) {
            int m = g.m0 + g.warpM * 64 + mf * 16 + half * 8 + g.gid;
            #pragma unroll
            for (int nf = 0; nf < 4; ++nf) {
                int n = g.n0 + g.warpN * 32 + nf * 8 + 2 * g.tig;
                *(float2*)&out[(size_t)m * DM + n] =
                    make_float2(c[mf][nf][half * 2], c[mf][nf][half * 2 + 1]);
            }
        }
    }
}

// ---------------------------------------------------------------------------
// Tensor-core causal flash attention — 64-row Q-tile, 128 thr, 3 CTAs/SM
// ---------------------------------------------------------------------------
#define FBUF 8192                      // u32 per buffer
#define FTC_SMEM (2 * FBUF * 4)        // 65536 B

__device__ __forceinline__ void fload(uint32_t sbase, int bh, int k0,
                                      int buf, int tid)
{
    const int kt = k0 >> 6;
    const uint32_t* ksrc = g_kp + (((size_t)bh * 32 + kt) * 1024) * 4;
    const uint32_t* vsrc = g_vp + (((size_t)bh * 32 + kt) * 1024) * 4;
    #pragma unroll
    for (int t = 0; t < 16; ++t) {
        int id = tid + t * 128;
        const uint32_t* src = (id < 1024) ? (ksrc + id * 4)
                                          : (vsrc + (id - 1024) * 4);
        CP_ASYNC16(sbase + buf * (FBUF * 4) + id * 16, src);
    }
    CP_COMMIT();
}

__global__ void __launch_bounds__(128, 3) flash_tc()
{
    extern __shared__ uint32_t smu[];
    const uint32_t sbase = smem_u32(smu);
    const int tid  = threadIdx.x;
    const int lane = tid & 31;
    const int warp = tid >> 5;
    const int gid  = lane >> 2;
    const int tig  = lane & 3;
    const int qt   = 31 - blockIdx.x;
    const int bh   = blockIdx.y;
    const int q0   = qt * 64;

    const float* qg = g_q + (size_t)bh * SEQ * DK;

    const float QSCALE = 0.125f * 1.44269504f;
    uint32_t qh[4][4], ql[4][4];
    #pragma unroll
    for (int ks = 0; ks < 4; ++ks) {
        #pragma unroll
        for (int j = 0; j < 4; ++j) {
            int row = q0 + warp * 16 + gid + (j & 1) * 8;
            int col = ks * 16 + 2 * tig + (j >> 1) * 8;
            float2 v = *(const float2*)&qg[(size_t)row * DK + col];
            v.x *= QSCALE; v.y *= QSCALE;
            qh[ks][j] = packpair(v.x, v.y, ql[ks][j]);
        }
    }

    float O[8][4];
    #pragma unroll
    for (int i = 0; i < 8; ++i)
        #pragma unroll
        for (int j = 0; j < 4; ++j) O[i][j] = 0.f;
    float lrow[2] = {0.f, 0.f};

    fload(sbase, bh, 0, 0, tid);

    for (int kt = 0; kt <= qt; ++kt) {
        const int buf = kt & 1;
        CP_WAIT0();
        __syncthreads();
        if (kt < qt)
            fload(sbase, bh, (kt + 1) * 64, buf ^ 1, tid);

        const uint4* Kb = (const uint4*)(smu + buf * FBUF);
        const uint4* Vb = Kb + 1024;

        float S[8][4];
        #pragma unroll
        for (int i = 0; i < 8; ++i)
            #pragma unroll
            for (int j = 0; j < 4; ++j) S[i][j] = 0.f;

        #pragma unroll
        for (int ks = 0; ks < 4; ++ks) {
            #pragma unroll
            for (int nf = 0; nf < 8; ++nf) {
                uint4 kw = Kb[(ks * 8 + nf) * 32 + lane];
                mma_bf16(S[nf], qh[ks], kw.x, kw.y);
                mma_bf16(S[nf], qh[ks], kw.z, kw.w);
                mma_bf16(S[nf], ql[ks], kw.x, kw.y);
            }
        }

        const bool diag = (kt == qt);
        #pragma unroll
        for (int nf = 0; nf < 8; ++nf)
            #pragma unroll
            for (int j = 0; j < 4; ++j) {
                float e = fexp2m(S[nf][j]);
                if (diag) {
                    int col = nf * 8 + 2 * tig + (j & 1);
                    int row = warp * 16 + gid + (j >> 1) * 8;
                    if (col > row) e = 0.f;
                }
                S[nf][j] = e;
                lrow[j >> 1] += e;
            }

        #pragma unroll
        for (int ks = 0; ks < 4; ++ks) {
            uint32_t aH[4], aL[4];
            #pragma unroll
            for (int h = 0; h < 2; ++h) {
                aH[2*h]   = packpair(S[2*ks+h][0], S[2*ks+h][1], aL[2*h]);
                aH[2*h+1] = packpair(S[2*ks+h][2], S[2*ks+h][3], aL[2*h+1]);
            }
            #pragma unroll
            for (int df = 0; df < 8; ++df) {
                uint4 vw = Vb[(ks * 8 + df) * 32 + lane];
                mma_bf16(O[df], aH, vw.x, vw.y);
                mma_bf16(O[df], aH, vw.z, vw.w);
                mma_bf16(O[df], aL, vw.x, vw.y);
            }
        }
    }

    const unsigned FULL = 0xffffffffu;
    #pragma unroll
    for (int r = 0; r < 2; ++r) {
        lrow[r] += __shfl_xor_sync(FULL, lrow[r], 1);
        lrow[r] += __shfl_xor_sync(FULL, lrow[r], 2);
    }
    const int b = bh >> 4;
    const int h = bh & 15;
    #pragma unroll
    for (int r = 0; r < 2; ++r) {
        float inv = 1.f / lrow[r];
        int s = q0 + warp * 16 + gid + r * 8;
        int m = b * SEQ + s;
        int mblk = m >> 7;
        int rr   = m & 127;
        int mfa  = rr >> 4;
        int gg   = rr & 7;
        int hlf  = (rr >> 3) & 1;
        int ch   = tig >> 1;
        int t    = 2 * (tig & 1);
        #pragma unroll
        for (int df = 0; df < 8; ++df) {
            int col = h * 64 + df * 8 + 2 * tig;
            int kt  = col >> 5;
            int ks  = df & 3;
            size_t base = ((size_t)mblk * 32 + kt) * 4096 +
                          (((mfa * 4 + ks) * 32 + gg * 4 + t) * 4 + 2 * ch + hlf);
            g_ao[base]     = rna_tf32(O[df][2 * r]     * inv);
            g_ao[base + 4] = rna_tf32(O[df][2 * r + 1] * inv);
        }
    }
}

// ---------------------------------------------------------------------------
// Launcher
// ---------------------------------------------------------------------------
extern "C" void kernel_launch(void* const* d_in, const int* in_sizes, int n_in,
                              void* d_out, int out_size)
{
    const float* x    = (const float*)d_in[0];
    const float* Wq   = (const float*)d_in[1];
    const float* Wk   = (const float*)d_in[2];
    const float* Wv   = (const float*)d_in[3];
    const float* Wo   = (const float*)d_in[4];
    const float* cosT = (const float*)d_in[5];
    const float* sinT = (const float*)d_in[6];
    const int*   pos  = (const int*)  d_in[7];
    float*       out  = (float*)d_out;

    cudaFuncSetAttribute(flash_tc,
                         cudaFuncAttributeMaxDynamicSharedMemorySize, FTC_SMEM);
    cudaFuncSetAttribute(gemm_qkv_fused,
                         cudaFuncAttributeMaxDynamicSharedMemorySize, GEMM_SMEM);
    cudaFuncSetAttribute(gemm_out,
                         cudaFuncAttributeMaxDynamicSharedMemorySize, GEMM_SMEM);

    perm_all<<<2048, 256>>>(x, Wq, Wk, Wv, Wo);

    dim3 qgrid(DM / 128, MTOT / 128, 3);   // (8, 32, 3)
    gemm_qkv_fused<<<qgrid, 256, GEMM_SMEM>>>(cosT, sinT, pos);

    dim3 fgrid(SEQ / 64, BATCH * NHEAD);   // (32, 32)
    flash_tc<<<fgrid, 128, FTC_SMEM>>>();

    dim3 ogrid(DM / 128, MTOT / 128);      // (8, 32)
    gemm_out<<<ogrid, 256, GEMM_SMEM>>>(out);
}